// round 7
// baseline (speedup 1.0000x reference)
#include <cuda_runtime.h>
#include <math.h>

#define T_LEN        32768
#define B_SEG        8
#define H_HEADS     8
#define C_COLS      1024
#define C4          256
#define RBLK        1024
#define ROWS_PER_BLK 32
#define NMLP        8

// ---------------- device scratch (zero-initialized at module load) -----------
__device__ float g_accum[B_SEG * C_COLS];   // segment sums; invariant: 0 at entry
__device__ float g_h1[B_SEG * 1024];
__device__ float g_h2[B_SEG * 256];
__device__ float g_h3[B_SEG * 512];
__device__ float g_h4[B_SEG * 128];
__device__ unsigned          g_cnt[6];
__device__ volatile unsigned g_gen[6];

__device__ __forceinline__ float silu(float v) { return v / (1.0f + expf(-v)); }

__device__ __forceinline__ void grid_bar(int id, unsigned target)
{
    __syncthreads();
    if (threadIdx.x == 0) {
        __threadfence();
        unsigned gen = g_gen[id];
        if (atomicAdd(&g_cnt[id], 1u) == target - 1u) {
            g_cnt[id] = 0u;
            __threadfence();
            g_gen[id] = gen + 1u;
        } else {
            while (g_gen[id] == gen) __nanosleep(32);
            __threadfence();
        }
    }
    __syncthreads();
}

// =================== K1: streaming segment-sum (unchanged) ====================
__global__ void __launch_bounds__(256) reduce_kernel(
    const float4* __restrict__ x4, const int* __restrict__ cu)
{
    const int tid = threadIdx.x;
    const int t0  = blockIdx.x * ROWS_PER_BLK;

    __shared__ int scu[B_SEG + 1];
    if (tid <= B_SEG) scu[tid] = cu[tid];
    __syncthreads();

    const int t1 = t0 + ROWS_PER_BLK - 1;
    int s0 = 0; while (s0 < B_SEG - 1 && t0 >= scu[s0 + 1]) s0++;
    int s1 = 0; while (s1 < B_SEG - 1 && t1 >= scu[s1 + 1]) s1++;

    const float4* xp = x4 + (size_t)t0 * C4 + tid;

    if (s0 == s1) {
        float4 a[8];
        #pragma unroll
        for (int i = 0; i < 8; i++) a[i] = make_float4(0.f,0.f,0.f,0.f);
        #pragma unroll
        for (int r = 0; r < ROWS_PER_BLK; r += 8) {
            #pragma unroll
            for (int u = 0; u < 8; u++) {
                float4 v = __ldcs(&xp[(r + u) * C4]);
                a[u].x += v.x; a[u].y += v.y; a[u].z += v.z; a[u].w += v.w;
            }
        }
        #pragma unroll
        for (int s = 4; s > 0; s >>= 1)
            #pragma unroll
            for (int i = 0; i < s; i++) {
                a[i].x += a[i+s].x; a[i].y += a[i+s].y;
                a[i].z += a[i+s].z; a[i].w += a[i+s].w;
            }
        float* dst = g_accum + s0 * C_COLS + tid * 4;
        atomicAdd(dst + 0, a[0].x); atomicAdd(dst + 1, a[0].y);
        atomicAdd(dst + 2, a[0].z); atomicAdd(dst + 3, a[0].w);
    } else {
        float4 a = make_float4(0.f,0.f,0.f,0.f);
        int seg = s0;
        int nxt = (seg < B_SEG - 1) ? scu[seg + 1] : 0x7fffffff;
        for (int r = 0; r < ROWS_PER_BLK; r++) {
            int t = t0 + r;
            if (t >= nxt) {
                float* dst = g_accum + seg * C_COLS + tid * 4;
                atomicAdd(dst + 0, a.x); atomicAdd(dst + 1, a.y);
                atomicAdd(dst + 2, a.z); atomicAdd(dst + 3, a.w);
                a = make_float4(0.f,0.f,0.f,0.f);
                while (seg < B_SEG - 1 && t >= scu[seg + 1]) seg++;
                nxt = (seg < B_SEG - 1) ? scu[seg + 1] : 0x7fffffff;
            }
            float4 v = __ldcs(&xp[r * C4]);
            a.x += v.x; a.y += v.y; a.z += v.z; a.w += v.w;
        }
        float* dst = g_accum + seg * C_COLS + tid * 4;
        atomicAdd(dst + 0, a.x); atomicAdd(dst + 1, a.y);
        atomicAdd(dst + 2, a.z); atomicAdd(dst + 3, a.w);
    }
}

// =================== K2: j-split MLP, 8 CTAs x 512 threads =====================
// Each CTA owns 1/8 of every layer's outputs for ALL 8 batches, so every
// weight element is loaded exactly once chip-wide (~300 KB per CTA).
__global__ void __launch_bounds__(512) mlp_kernel(
    const int* __restrict__ cu,
    const float* __restrict__ w1, const float* __restrict__ b1,
    const float* __restrict__ w2, const float* __restrict__ b2,
    const float* __restrict__ w3, const float* __restrict__ b3,
    const float* __restrict__ w4, const float* __restrict__ b4,
    const float* __restrict__ w5, const float* __restrict__ b5,
    float* __restrict__ out)
{
    __shared__ float  xs[4096];        // activations staged as xs[k*8 + b]
    __shared__ float4 red4[1024];      // 16 KB k-slice partials
    __shared__ float  inv_s[8];
    __shared__ float  l0[128], l1[128];

    const int tid = threadIdx.x;
    const int c   = blockIdx.x;        // CTA = j-slice index; also batch id in L5

    // ---- pooled mean: xs[k*8+b], k in [0,128) --------------------------------
    if (tid < B_SEG) {
        int cnt = cu[tid + 1] - cu[tid];
        if (cnt < 1) cnt = 1;
        inv_s[tid] = 1.0f / ((float)cnt * (float)H_HEADS);
    }
    __syncthreads();
    for (int i = tid; i < 1024; i += 512) {
        int k = i >> 3, b = i & 7;
        float s = 0.f;
        #pragma unroll
        for (int h = 0; h < H_HEADS; h++)
            s += __ldcg(&g_accum[b * C_COLS + h * 128 + k]);
        xs[i] = s * inv_s[b];
    }
    __syncthreads();

    float4 acc[8];

    // ===== L1: K=128 -> N=1024. j-slice 128. lanes = 4ks x 8j4; NK=16, klen=8 ==
    {
        const int j4w = tid & 7, ksw = (tid >> 3) & 3, warp = tid >> 5;
        const int jblk = warp & 3, ksc = warp >> 2;            // jblk<4, ksc<4
        const int j4l = jblk * 8 + j4w;                        // 0..31
        const int k0  = (ksc * 4 + ksw) * 8;
        const float* wp = w1 + c * 128 + j4l * 4;

        float4 wv[8];
        #pragma unroll
        for (int u = 0; u < 8; u++) wv[u] = *(const float4*)&wp[(k0 + u) * 1024];
        #pragma unroll
        for (int b = 0; b < 8; b++) acc[b] = make_float4(0.f,0.f,0.f,0.f);
        #pragma unroll
        for (int u = 0; u < 8; u++) {
            const float* xr = &xs[(k0 + u) * 8];
            #pragma unroll
            for (int b = 0; b < 8; b++) {
                float xv = xr[b];
                acc[b].x += xv * wv[u].x; acc[b].y += xv * wv[u].y;
                acc[b].z += xv * wv[u].z; acc[b].w += xv * wv[u].w;
            }
        }
        #pragma unroll
        for (int off = 8; off <= 16; off <<= 1)
            #pragma unroll
            for (int b = 0; b < 8; b++) {
                acc[b].x += __shfl_xor_sync(0xffffffff, acc[b].x, off);
                acc[b].y += __shfl_xor_sync(0xffffffff, acc[b].y, off);
                acc[b].z += __shfl_xor_sync(0xffffffff, acc[b].z, off);
                acc[b].w += __shfl_xor_sync(0xffffffff, acc[b].w, off);
            }
        if (ksw == 0)
            #pragma unroll
            for (int b = 0; b < 8; b++)
                red4[(j4l * 4 + ksc) * 8 + b] = acc[b];
        __syncthreads();
        if (tid < 256) {
            const int jl = tid >> 3, b = tid & 7;
            float4 s = make_float4(0.f,0.f,0.f,0.f);
            #pragma unroll
            for (int q = 0; q < 4; q++) {
                float4 v = red4[(jl * 4 + q) * 8 + b];
                s.x += v.x; s.y += v.y; s.z += v.z; s.w += v.w;
            }
            float4 bias = *(const float4*)&b1[c * 128 + jl * 4];
            float4 o;
            o.x = silu(s.x + bias.x); o.y = silu(s.y + bias.y);
            o.z = silu(s.z + bias.z); o.w = silu(s.w + bias.w);
            *(float4*)&g_h1[b * 1024 + c * 128 + jl * 4] = o;
        }
    }
    grid_bar(1, NMLP);

    // reset segment accumulator (all CTAs finished reading g_accum)
    for (int i = tid; i < 1024; i += 512)
        g_accum[c * 1024 + i] = 0.f;

    // ===== L2: K=1024 -> N=256. j-slice 32. two 512-k passes; NK=64, klen=8 ====
    {
        const int j4w = tid & 7, ksw = (tid >> 3) & 3, ksc = tid >> 5;  // ksc<16
        const int ks  = ksc * 4 + ksw;                                  // 0..63
        #pragma unroll
        for (int b = 0; b < 8; b++) acc[b] = make_float4(0.f,0.f,0.f,0.f);

        #pragma unroll
        for (int p = 0; p < 2; p++) {
            __syncthreads();
            for (int i = tid; i < 4096; i += 512) {
                int k = i >> 3, b = i & 7;
                xs[i] = __ldcg(&g_h1[b * 1024 + p * 512 + k]);
            }
            __syncthreads();
            const int k0 = ks * 8;
            const float* wp = w2 + (p * 512) * 256 + c * 32 + j4w * 4;
            float4 wv[8];
            #pragma unroll
            for (int u = 0; u < 8; u++) wv[u] = *(const float4*)&wp[(k0 + u) * 256];
            #pragma unroll
            for (int u = 0; u < 8; u++) {
                const float* xr = &xs[(k0 + u) * 8];
                #pragma unroll
                for (int b = 0; b < 8; b++) {
                    float xv = xr[b];
                    acc[b].x += xv * wv[u].x; acc[b].y += xv * wv[u].y;
                    acc[b].z += xv * wv[u].z; acc[b].w += xv * wv[u].w;
                }
            }
        }
        #pragma unroll
        for (int off = 8; off <= 16; off <<= 1)
            #pragma unroll
            for (int b = 0; b < 8; b++) {
                acc[b].x += __shfl_xor_sync(0xffffffff, acc[b].x, off);
                acc[b].y += __shfl_xor_sync(0xffffffff, acc[b].y, off);
                acc[b].z += __shfl_xor_sync(0xffffffff, acc[b].z, off);
                acc[b].w += __shfl_xor_sync(0xffffffff, acc[b].w, off);
            }
        if (ksw == 0)
            #pragma unroll
            for (int b = 0; b < 8; b++)
                red4[(j4w * 16 + ksc) * 8 + b] = acc[b];
        __syncthreads();
        if (tid < 64) {
            const int jl = tid >> 3, b = tid & 7;
            float4 s = make_float4(0.f,0.f,0.f,0.f);
            #pragma unroll
            for (int q = 0; q < 16; q++) {
                float4 v = red4[(jl * 16 + q) * 8 + b];
                s.x += v.x; s.y += v.y; s.z += v.z; s.w += v.w;
            }
            float4 bias = *(const float4*)&b2[c * 32 + jl * 4];
            float4 o;
            o.x = s.x + bias.x; o.y = s.y + bias.y;
            o.z = s.z + bias.z; o.w = s.w + bias.w;          // no activation
            *(float4*)&g_h2[b * 256 + c * 32 + jl * 4] = o;
        }
    }
    grid_bar(2, NMLP);

    // ===== L3: K=256 -> N=512. j-slice 64. NK=32, klen=8 =======================
    {
        for (int i = tid; i < 2048; i += 512) {
            int k = i >> 3, b = i & 7;
            xs[i] = __ldcg(&g_h2[b * 256 + k]);
        }
        __syncthreads();

        const int j4w = tid & 7, ksw = (tid >> 3) & 3, warp = tid >> 5;
        const int jblk = warp & 1, ksc = warp >> 1;            // jblk<2, ksc<8
        const int j4l = jblk * 8 + j4w;                        // 0..15
        const int k0  = (ksc * 4 + ksw) * 8;
        const float* wp = w3 + c * 64 + j4l * 4;

        float4 wv[8];
        #pragma unroll
        for (int u = 0; u < 8; u++) wv[u] = *(const float4*)&wp[(k0 + u) * 512];
        #pragma unroll
        for (int b = 0; b < 8; b++) acc[b] = make_float4(0.f,0.f,0.f,0.f);
        #pragma unroll
        for (int u = 0; u < 8; u++) {
            const float* xr = &xs[(k0 + u) * 8];
            #pragma unroll
            for (int b = 0; b < 8; b++) {
                float xv = xr[b];
                acc[b].x += xv * wv[u].x; acc[b].y += xv * wv[u].y;
                acc[b].z += xv * wv[u].z; acc[b].w += xv * wv[u].w;
            }
        }
        #pragma unroll
        for (int off = 8; off <= 16; off <<= 1)
            #pragma unroll
            for (int b = 0; b < 8; b++) {
                acc[b].x += __shfl_xor_sync(0xffffffff, acc[b].x, off);
                acc[b].y += __shfl_xor_sync(0xffffffff, acc[b].y, off);
                acc[b].z += __shfl_xor_sync(0xffffffff, acc[b].z, off);
                acc[b].w += __shfl_xor_sync(0xffffffff, acc[b].w, off);
            }
        if (ksw == 0)
            #pragma unroll
            for (int b = 0; b < 8; b++)
                red4[(j4l * 8 + ksc) * 8 + b] = acc[b];
        __syncthreads();
        if (tid < 128) {
            const int jl = tid >> 3, b = tid & 7;
            float4 s = make_float4(0.f,0.f,0.f,0.f);
            #pragma unroll
            for (int q = 0; q < 8; q++) {
                float4 v = red4[(jl * 8 + q) * 8 + b];
                s.x += v.x; s.y += v.y; s.z += v.z; s.w += v.w;
            }
            float4 bias = *(const float4*)&b3[c * 64 + jl * 4];
            float4 o;
            o.x = silu(s.x + bias.x); o.y = silu(s.y + bias.y);
            o.z = silu(s.z + bias.z); o.w = silu(s.w + bias.w);
            *(float4*)&g_h3[b * 512 + c * 64 + jl * 4] = o;
        }
    }
    grid_bar(3, NMLP);

    // ===== L4: K=512 -> N=128. j-slice 16. lanes = 8ks x 4j4; NK=128, klen=4 ===
    {
        for (int i = tid; i < 4096; i += 512) {
            int k = i >> 3, b = i & 7;
            xs[i] = __ldcg(&g_h3[b * 512 + k]);
        }
        __syncthreads();

        const int j4w = tid & 3, ksw = (tid >> 2) & 7, ksc = tid >> 5;  // ksc<16
        const int k0  = (ksc * 8 + ksw) * 4;
        const float* wp = w4 + c * 16 + j4w * 4;

        float4 wv[4];
        #pragma unroll
        for (int u = 0; u < 4; u++) wv[u] = *(const float4*)&wp[(k0 + u) * 128];
        #pragma unroll
        for (int b = 0; b < 8; b++) acc[b] = make_float4(0.f,0.f,0.f,0.f);
        #pragma unroll
        for (int u = 0; u < 4; u++) {
            const float* xr = &xs[(k0 + u) * 8];
            #pragma unroll
            for (int b = 0; b < 8; b++) {
                float xv = xr[b];
                acc[b].x += xv * wv[u].x; acc[b].y += xv * wv[u].y;
                acc[b].z += xv * wv[u].z; acc[b].w += xv * wv[u].w;
            }
        }
        #pragma unroll
        for (int off = 4; off <= 16; off <<= 1)
            #pragma unroll
            for (int b = 0; b < 8; b++) {
                acc[b].x += __shfl_xor_sync(0xffffffff, acc[b].x, off);
                acc[b].y += __shfl_xor_sync(0xffffffff, acc[b].y, off);
                acc[b].z += __shfl_xor_sync(0xffffffff, acc[b].z, off);
                acc[b].w += __shfl_xor_sync(0xffffffff, acc[b].w, off);
            }
        if (ksw == 0)
            #pragma unroll
            for (int b = 0; b < 8; b++)
                red4[(j4w * 16 + ksc) * 8 + b] = acc[b];
        __syncthreads();
        if (tid < 32) {
            const int jl = tid >> 3, b = tid & 7;
            float4 s = make_float4(0.f,0.f,0.f,0.f);
            #pragma unroll
            for (int q = 0; q < 16; q++) {
                float4 v = red4[(jl * 16 + q) * 8 + b];
                s.x += v.x; s.y += v.y; s.z += v.z; s.w += v.w;
            }
            float4 bias = *(const float4*)&b4[c * 16 + jl * 4];
            float4 o;
            o.x = silu(s.x + bias.x); o.y = silu(s.y + bias.y);
            o.z = silu(s.z + bias.z); o.w = silu(s.w + bias.w);
            *(float4*)&g_h4[b * 128 + c * 16 + jl * 4] = o;
        }
    }
    grid_bar(4, NMLP);

    // ===== L5: CTA c = batch c. 128 -> 2, argmax, output ========================
    if (tid < 128) {
        float v = __ldcg(&g_h4[c * 128 + tid]);
        l0[tid] = v * w5[tid * 2 + 0];
        l1[tid] = v * w5[tid * 2 + 1];
    }
    __syncthreads();
    #pragma unroll
    for (int stride = 64; stride > 0; stride >>= 1) {
        if (tid < stride) {
            l0[tid] += l0[tid + stride];
            l1[tid] += l1[tid + stride];
        }
        __syncthreads();
    }
    if (tid == 0) {
        float lg0 = l0[0] + b5[0];
        float lg1 = l1[0] + b5[1];
        float z = (lg1 > lg0) ? 1.0f : 0.0f;     // argmax; tie -> class 0
        #pragma unroll
        for (int h = 0; h < H_HEADS; h++)
            out[c * H_HEADS + h] = z;
    }
}

// ---------------- launch --------------------------------------------------------
extern "C" void kernel_launch(void* const* d_in, const int* in_sizes, int n_in,
                              void* d_out, int out_size)
{
    const float* x  = (const float*)d_in[0];
    const int*   cu = (const int*)  d_in[1];
    const float* w1 = (const float*)d_in[2];
    const float* b1 = (const float*)d_in[3];
    const float* w2 = (const float*)d_in[4];
    const float* b2 = (const float*)d_in[5];
    const float* w3 = (const float*)d_in[6];
    const float* b3 = (const float*)d_in[7];
    const float* w4 = (const float*)d_in[8];
    const float* b4 = (const float*)d_in[9];
    const float* w5 = (const float*)d_in[10];
    const float* b5 = (const float*)d_in[11];

    reduce_kernel<<<RBLK, 256>>>((const float4*)x, cu);
    mlp_kernel<<<NMLP, 512>>>(cu, w1, b1, w2, b2, w3, b3, w4, b4, w5, b5,
                              (float*)d_out);
}

// round 8
// speedup vs baseline: 1.2152x; 1.2152x over previous
#include <cuda_runtime.h>
#include <math.h>
#include <stdint.h>

#define T_LEN        32768
#define B_SEG        8
#define H_HEADS      8
#define C_COLS       1024
#define C4           256
#define RBLK         1024
#define ROWS_PER_BLK 32
#define CLUSTER      4

__device__ float g_accum[B_SEG * C_COLS];   // segment sums; invariant: 0 at entry

__device__ __forceinline__ float silu(float v) { return v / (1.0f + expf(-v)); }

// =================== K1: streaming segment-sum (unchanged from R6) ============
__global__ void __launch_bounds__(256) reduce_kernel(
    const float4* __restrict__ x4, const int* __restrict__ cu)
{
    const int tid = threadIdx.x;
    const int t0  = blockIdx.x * ROWS_PER_BLK;

    __shared__ int scu[B_SEG + 1];
    if (tid <= B_SEG) scu[tid] = cu[tid];
    __syncthreads();

    const int t1 = t0 + ROWS_PER_BLK - 1;
    int s0 = 0; while (s0 < B_SEG - 1 && t0 >= scu[s0 + 1]) s0++;
    int s1 = 0; while (s1 < B_SEG - 1 && t1 >= scu[s1 + 1]) s1++;

    const float4* xp = x4 + (size_t)t0 * C4 + tid;

    if (s0 == s1) {
        float4 a[8];
        #pragma unroll
        for (int i = 0; i < 8; i++) a[i] = make_float4(0.f,0.f,0.f,0.f);
        #pragma unroll
        for (int r = 0; r < ROWS_PER_BLK; r += 8) {
            #pragma unroll
            for (int u = 0; u < 8; u++) {
                float4 v = __ldcs(&xp[(r + u) * C4]);
                a[u].x += v.x; a[u].y += v.y; a[u].z += v.z; a[u].w += v.w;
            }
        }
        #pragma unroll
        for (int s = 4; s > 0; s >>= 1)
            #pragma unroll
            for (int i = 0; i < s; i++) {
                a[i].x += a[i+s].x; a[i].y += a[i+s].y;
                a[i].z += a[i+s].z; a[i].w += a[i+s].w;
            }
        float* dst = g_accum + s0 * C_COLS + tid * 4;
        atomicAdd(dst + 0, a[0].x); atomicAdd(dst + 1, a[0].y);
        atomicAdd(dst + 2, a[0].z); atomicAdd(dst + 3, a[0].w);
    } else {
        float4 a = make_float4(0.f,0.f,0.f,0.f);
        int seg = s0;
        int nxt = (seg < B_SEG - 1) ? scu[seg + 1] : 0x7fffffff;
        for (int r = 0; r < ROWS_PER_BLK; r++) {
            int t = t0 + r;
            if (t >= nxt) {
                float* dst = g_accum + seg * C_COLS + tid * 4;
                atomicAdd(dst + 0, a.x); atomicAdd(dst + 1, a.y);
                atomicAdd(dst + 2, a.z); atomicAdd(dst + 3, a.w);
                a = make_float4(0.f,0.f,0.f,0.f);
                while (seg < B_SEG - 1 && t >= scu[seg + 1]) seg++;
                nxt = (seg < B_SEG - 1) ? scu[seg + 1] : 0x7fffffff;
            }
            float4 v = __ldcs(&xp[r * C4]);
            a.x += v.x; a.y += v.y; a.z += v.z; a.w += v.w;
        }
        float* dst = g_accum + seg * C_COLS + tid * 4;
        atomicAdd(dst + 0, a.x); atomicAdd(dst + 1, a.y);
        atomicAdd(dst + 2, a.z); atomicAdd(dst + 3, a.w);
    }
}

// =================== cluster helpers ==========================================
__device__ __forceinline__ uint32_t smem_u32(const void* p) {
    uint32_t a;
    asm("{ .reg .u64 t; cvta.to.shared.u64 t, %1; cvt.u32.u64 %0, t; }"
        : "=r"(a) : "l"(p));
    return a;
}
__device__ __forceinline__ uint32_t ctarank() {
    uint32_t r; asm("mov.u32 %0, %%cluster_ctarank;" : "=r"(r)); return r;
}
__device__ __forceinline__ void st_cluster4(uint32_t addr, uint32_t rank, float4 v) {
    asm volatile(
        "{ .reg .u32 ra;\n"
        "  mapa.shared::cluster.u32 ra, %0, %1;\n"
        "  st.shared::cluster.v4.f32 [ra], {%2, %3, %4, %5}; }"
        :: "r"(addr), "r"(rank), "f"(v.x), "f"(v.y), "f"(v.z), "f"(v.w)
        : "memory");
}
#define CLUSTER_SYNC() do { \
    asm volatile("barrier.cluster.arrive.aligned;" ::: "memory"); \
    asm volatile("barrier.cluster.wait.aligned;"   ::: "memory"); \
} while (0)

// Generic j-sliced layer: this CTA computes SLICE=NJ4*4 outputs of an N-wide
// layer for ONE batch, reading xin[K] from smem, broadcasting its slice into
// xnext (same offset) of ALL cluster CTAs via DSMEM.
template<int NJ4, int NKS, int KLEN, int N, bool ACT>
__device__ __forceinline__ void do_layer(
    const float* __restrict__ W, const float* __restrict__ Bv,
    int rank, int tid, const float* __restrict__ xin,
    float4* __restrict__ red, uint32_t xnext_u32)
{
    constexpr int SLICE = NJ4 * 4;
    const int j4 = tid & (NJ4 - 1);
    const int ks = tid >> __popc(NJ4 - 1);           // tid / NJ4 (NJ4 pow2)
    const int k0 = ks * KLEN;
    const float* wp = W + rank * SLICE + j4 * 4;

    float4 acc = make_float4(0.f, 0.f, 0.f, 0.f);
    #pragma unroll
    for (int kb = 0; kb < KLEN; kb += 8) {
        float4 wv[8];
        #pragma unroll
        for (int u = 0; u < 8; u++)
            wv[u] = *(const float4*)&wp[(size_t)(k0 + kb + u) * N];
        #pragma unroll
        for (int u = 0; u < 8; u++) {
            float xv = xin[k0 + kb + u];
            acc.x += xv * wv[u].x; acc.y += xv * wv[u].y;
            acc.z += xv * wv[u].z; acc.w += xv * wv[u].w;
        }
    }
    red[ks * NJ4 + j4] = acc;
    __syncthreads();

    if (tid < NJ4) {
        float4 s = make_float4(0.f, 0.f, 0.f, 0.f);
        #pragma unroll
        for (int q = 0; q < NKS; q++) {
            float4 v = red[q * NJ4 + tid];
            s.x += v.x; s.y += v.y; s.z += v.z; s.w += v.w;
        }
        float4 bias = *(const float4*)&Bv[rank * SLICE + tid * 4];
        float4 o;
        if (ACT) {
            o.x = silu(s.x + bias.x); o.y = silu(s.y + bias.y);
            o.z = silu(s.z + bias.z); o.w = silu(s.w + bias.w);
        } else {
            o.x = s.x + bias.x; o.y = s.y + bias.y;
            o.z = s.z + bias.z; o.w = s.w + bias.w;
        }
        uint32_t a = xnext_u32 + (uint32_t)(rank * SLICE + tid * 4) * 4u;
        #pragma unroll
        for (uint32_t r = 0; r < CLUSTER; r++)
            st_cluster4(a, r, o);
    }
}

// =================== K2: clustered MLP ========================================
// 8 clusters x 4 CTAs x 256 threads. Cluster c = batch c; CTA rank = j-slice.
__global__ void __launch_bounds__(256) __cluster_dims__(CLUSTER, 1, 1)
mlp_kernel(
    const int* __restrict__ cu,
    const float* __restrict__ w1, const float* __restrict__ b1,
    const float* __restrict__ w2, const float* __restrict__ b2,
    const float* __restrict__ w3, const float* __restrict__ b3,
    const float* __restrict__ w4, const float* __restrict__ b4,
    const float* __restrict__ w5, const float* __restrict__ b5,
    float* __restrict__ out)
{
    __shared__ float  xs0[1024];      // pooled -> h2 -> h4
    __shared__ float  xs1[1024];      // h1 -> h3
    __shared__ float4 red[256];       // 4 KB k-slice partials
    __shared__ float  l0[128], l1[128];

    const int tid  = threadIdx.x;
    const int b    = blockIdx.x >> 2;           // cluster id = batch
    const int rank = (int)ctarank();

    const uint32_t xs0_u32 = smem_u32(xs0);
    const uint32_t xs1_u32 = smem_u32(xs1);

    // ---- pooled mean (every CTA builds its own full copy) --------------------
    {
        int cnt = cu[b + 1] - cu[b];
        if (cnt < 1) cnt = 1;
        const float inv = 1.0f / ((float)cnt * (float)H_HEADS);
        if (tid < 128) {
            float s = 0.f;
            #pragma unroll
            for (int h = 0; h < H_HEADS; h++)
                s += __ldcg(&g_accum[b * C_COLS + h * 128 + tid]);
            xs0[tid] = s * inv;
        }
    }
    __syncthreads();
    CLUSTER_SYNC();                    // all CTAs done reading g_accum[b]

    // reset this batch's accumulator (each rank clears a quarter)
    for (int i = tid; i < 256; i += 256)
        g_accum[b * C_COLS + rank * 256 + i] = 0.f;

    // ---- L1: 128 -> 1024, silu. slice 256. 64 j4 x 4 ks (k=32) ---------------
    do_layer< 64,  4, 32, 1024, true >(w1, b1, rank, tid, xs0, red, xs1_u32);
    CLUSTER_SYNC();

    // ---- L2: 1024 -> 256, no act. slice 64. 16 j4 x 16 ks (k=64) -------------
    do_layer< 16, 16, 64,  256, false>(w2, b2, rank, tid, xs1, red, xs0_u32);
    CLUSTER_SYNC();

    // ---- L3: 256 -> 512, silu. slice 128. 32 j4 x 8 ks (k=32) ----------------
    do_layer< 32,  8, 32,  512, true >(w3, b3, rank, tid, xs0, red, xs1_u32);
    CLUSTER_SYNC();

    // ---- L4: 512 -> 128, silu. slice 32. 8 j4 x 32 ks (k=16) -----------------
    do_layer<  8, 32, 16,  128, true >(w4, b4, rank, tid, xs1, red, xs0_u32);
    CLUSTER_SYNC();

    // ---- L5: 128 -> 2, argmax, output (rank 0 only) --------------------------
    if (rank == 0) {
        if (tid < 128) {
            float v = xs0[tid];
            l0[tid] = v * w5[tid * 2 + 0];
            l1[tid] = v * w5[tid * 2 + 1];
        }
        __syncthreads();
        #pragma unroll
        for (int stride = 64; stride > 0; stride >>= 1) {
            if (tid < stride) {
                l0[tid] += l0[tid + stride];
                l1[tid] += l1[tid + stride];
            }
            __syncthreads();
        }
        if (tid == 0) {
            float lg0 = l0[0] + b5[0];
            float lg1 = l1[0] + b5[1];
            float z = (lg1 > lg0) ? 1.0f : 0.0f;   // argmax; tie -> class 0
            #pragma unroll
            for (int h = 0; h < H_HEADS; h++)
                out[b * H_HEADS + h] = z;
        }
    }
    // final cluster sync: no CTA exits while peers may still write its smem
    CLUSTER_SYNC();
}

// ---------------- launch --------------------------------------------------------
extern "C" void kernel_launch(void* const* d_in, const int* in_sizes, int n_in,
                              void* d_out, int out_size)
{
    const float* x  = (const float*)d_in[0];
    const int*   cu = (const int*)  d_in[1];
    const float* w1 = (const float*)d_in[2];
    const float* b1 = (const float*)d_in[3];
    const float* w2 = (const float*)d_in[4];
    const float* b2 = (const float*)d_in[5];
    const float* w3 = (const float*)d_in[6];
    const float* b3 = (const float*)d_in[7];
    const float* w4 = (const float*)d_in[8];
    const float* b4 = (const float*)d_in[9];
    const float* w5 = (const float*)d_in[10];
    const float* b5 = (const float*)d_in[11];

    reduce_kernel<<<RBLK, 256>>>((const float4*)x, cu);
    mlp_kernel<<<B_SEG * CLUSTER, 256>>>(cu, w1, b1, w2, b2, w3, b3,
                                         w4, b4, w5, b5, (float*)d_out);
}

// round 9
// speedup vs baseline: 1.2439x; 1.0237x over previous
#include <cuda_runtime.h>
#include <math.h>
#include <stdint.h>

#define T_LEN        32768
#define B_SEG        8
#define H_HEADS      8
#define C_COLS       1024
#define C4           256
#define RBLK         1024
#define ROWS_PER_BLK 32
#define CLUSTER      4

__device__ float g_accum[B_SEG * C_COLS];   // segment sums; invariant: 0 at entry

__device__ __forceinline__ float silu(float v) { return v / (1.0f + expf(-v)); }

// =================== K1: streaming segment-sum (unchanged) ====================
__global__ void __launch_bounds__(256) reduce_kernel(
    const float4* __restrict__ x4, const int* __restrict__ cu)
{
    const int tid = threadIdx.x;
    const int t0  = blockIdx.x * ROWS_PER_BLK;

    __shared__ int scu[B_SEG + 1];
    if (tid <= B_SEG) scu[tid] = cu[tid];
    __syncthreads();

    const int t1 = t0 + ROWS_PER_BLK - 1;
    int s0 = 0; while (s0 < B_SEG - 1 && t0 >= scu[s0 + 1]) s0++;
    int s1 = 0; while (s1 < B_SEG - 1 && t1 >= scu[s1 + 1]) s1++;

    const float4* xp = x4 + (size_t)t0 * C4 + tid;

    if (s0 == s1) {
        float4 a[8];
        #pragma unroll
        for (int i = 0; i < 8; i++) a[i] = make_float4(0.f,0.f,0.f,0.f);
        #pragma unroll
        for (int r = 0; r < ROWS_PER_BLK; r += 8) {
            #pragma unroll
            for (int u = 0; u < 8; u++) {
                float4 v = __ldcs(&xp[(r + u) * C4]);
                a[u].x += v.x; a[u].y += v.y; a[u].z += v.z; a[u].w += v.w;
            }
        }
        #pragma unroll
        for (int s = 4; s > 0; s >>= 1)
            #pragma unroll
            for (int i = 0; i < s; i++) {
                a[i].x += a[i+s].x; a[i].y += a[i+s].y;
                a[i].z += a[i+s].z; a[i].w += a[i+s].w;
            }
        float* dst = g_accum + s0 * C_COLS + tid * 4;
        atomicAdd(dst + 0, a[0].x); atomicAdd(dst + 1, a[0].y);
        atomicAdd(dst + 2, a[0].z); atomicAdd(dst + 3, a[0].w);
    } else {
        float4 a = make_float4(0.f,0.f,0.f,0.f);
        int seg = s0;
        int nxt = (seg < B_SEG - 1) ? scu[seg + 1] : 0x7fffffff;
        for (int r = 0; r < ROWS_PER_BLK; r++) {
            int t = t0 + r;
            if (t >= nxt) {
                float* dst = g_accum + seg * C_COLS + tid * 4;
                atomicAdd(dst + 0, a.x); atomicAdd(dst + 1, a.y);
                atomicAdd(dst + 2, a.z); atomicAdd(dst + 3, a.w);
                a = make_float4(0.f,0.f,0.f,0.f);
                while (seg < B_SEG - 1 && t >= scu[seg + 1]) seg++;
                nxt = (seg < B_SEG - 1) ? scu[seg + 1] : 0x7fffffff;
            }
            float4 v = __ldcs(&xp[r * C4]);
            a.x += v.x; a.y += v.y; a.z += v.z; a.w += v.w;
        }
        float* dst = g_accum + seg * C_COLS + tid * 4;
        atomicAdd(dst + 0, a.x); atomicAdd(dst + 1, a.y);
        atomicAdd(dst + 2, a.z); atomicAdd(dst + 3, a.w);
    }
}

// =================== helpers ==================================================
__device__ __forceinline__ uint32_t smem_u32(const void* p) {
    uint32_t a;
    asm("{ .reg .u64 t; cvta.to.shared.u64 t, %1; cvt.u32.u64 %0, t; }"
        : "=r"(a) : "l"(p));
    return a;
}
__device__ __forceinline__ uint32_t ctarank() {
    uint32_t r; asm("mov.u32 %0, %%cluster_ctarank;" : "=r"(r)); return r;
}
__device__ __forceinline__ void st_cluster4(uint32_t addr, uint32_t rank, float4 v) {
    asm volatile(
        "{ .reg .u32 ra;\n"
        "  mapa.shared::cluster.u32 ra, %0, %1;\n"
        "  st.shared::cluster.v4.f32 [ra], {%2, %3, %4, %5}; }"
        :: "r"(addr), "r"(rank), "f"(v.x), "f"(v.y), "f"(v.z), "f"(v.w)
        : "memory");
}
#define CLUSTER_SYNC() do { \
    asm volatile("barrier.cluster.arrive.aligned;" ::: "memory"); \
    asm volatile("barrier.cluster.wait.aligned;"   ::: "memory"); \
} while (0)

__device__ __forceinline__ void cp_async16(uint32_t dst, const void* src) {
    asm volatile("cp.async.cg.shared.global [%0], [%1], 16;"
                 :: "r"(dst), "l"(src) : "memory");
}
__device__ __forceinline__ void cp_commit() {
    asm volatile("cp.async.commit_group;" ::: "memory");
}
template<int N> __device__ __forceinline__ void cp_wait() {
    asm volatile("cp.async.wait_group %0;" :: "n"(N) : "memory");
}

// Weight tile staged per iteration: 4096 floats = 16 KB, double buffered.
#define TILE_FLOATS 4096
#define TILE_BYTES  16384

// j-sliced layer with cp.async double-buffered weight staging.
// This CTA computes SLICE outputs of the N-wide layer for one batch.
template<int K, int N, int SLICE, int KTILE, bool ACT>
__device__ __forceinline__ void do_layer_async(
    const float* __restrict__ W, const float* __restrict__ Bv,
    int rank, int tid, const float* __restrict__ xin,
    float* __restrict__ wbuf, uint32_t wbuf_u32,
    float4* __restrict__ red, uint32_t xnext_u32)
{
    constexpr int NJ4  = SLICE / 4;      // j-quads
    constexpr int NKS  = 256 / NJ4;      // k-slices
    constexpr int KLEN = KTILE / NKS;    // rows per thread per tile (= 4)
    constexpr int NT   = K / KTILE;      // tiles
    constexpr int CROW = SLICE / 4;      // 16B chunks per weight row
    constexpr int CPT  = TILE_FLOATS / 4 / 256;   // chunks per thread (= 4)

    const float* wg = W + rank * SLICE;

    auto prefetch = [&](int t, int buf) {
        #pragma unroll
        for (int c = 0; c < CPT; c++) {
            int chunk = c * 256 + tid;
            int row   = chunk / CROW;
            int col   = chunk - row * CROW;
            const float* src = wg + (size_t)(t * KTILE + row) * N + col * 4;
            uint32_t dst = wbuf_u32 + buf * TILE_BYTES
                         + (uint32_t)(row * SLICE + col * 4) * 4u;
            cp_async16(dst, src);
        }
        cp_commit();
    };

    const int j4 = tid & (NJ4 - 1);
    const int ks = tid / NJ4;

    float4 acc = make_float4(0.f, 0.f, 0.f, 0.f);
    prefetch(0, 0);

    #pragma unroll
    for (int t = 0; t < NT; t++) {
        if (t + 1 < NT) {
            prefetch(t + 1, (t + 1) & 1);
            cp_wait<1>();
        } else {
            cp_wait<0>();
        }
        __syncthreads();                         // tile t visible to all
        const float* wt = wbuf + (t & 1) * TILE_FLOATS + (ks * KLEN) * SLICE + j4 * 4;
        const float* xk = xin + t * KTILE + ks * KLEN;
        #pragma unroll
        for (int u = 0; u < KLEN; u++) {
            float4 wv = *(const float4*)&wt[u * SLICE];
            float  xv = xk[u];
            acc.x += xv * wv.x; acc.y += xv * wv.y;
            acc.z += xv * wv.z; acc.w += xv * wv.w;
        }
        __syncthreads();                         // reads done before overwrite
    }

    red[ks * NJ4 + j4] = acc;
    __syncthreads();

    if (tid < NJ4) {
        float4 s = make_float4(0.f, 0.f, 0.f, 0.f);
        #pragma unroll
        for (int q = 0; q < NKS; q++) {
            float4 v = red[q * NJ4 + tid];
            s.x += v.x; s.y += v.y; s.z += v.z; s.w += v.w;
        }
        float4 bias = *(const float4*)&Bv[rank * SLICE + tid * 4];
        float4 o;
        if (ACT) {
            o.x = silu(s.x + bias.x); o.y = silu(s.y + bias.y);
            o.z = silu(s.z + bias.z); o.w = silu(s.w + bias.w);
        } else {
            o.x = s.x + bias.x; o.y = s.y + bias.y;
            o.z = s.z + bias.z; o.w = s.w + bias.w;
        }
        uint32_t a = xnext_u32 + (uint32_t)(rank * SLICE + tid * 4) * 4u;
        #pragma unroll
        for (uint32_t r = 0; r < CLUSTER; r++)
            st_cluster4(a, r, o);
    }
    __syncthreads();
}

// =================== K2: clustered MLP with async weight staging ==============
// 8 clusters x 4 CTAs x 256 threads. Cluster c = batch c; CTA rank = j-slice.
__global__ void __launch_bounds__(256) __cluster_dims__(CLUSTER, 1, 1)
mlp_kernel(
    const int* __restrict__ cu,
    const float* __restrict__ w1, const float* __restrict__ b1,
    const float* __restrict__ w2, const float* __restrict__ b2,
    const float* __restrict__ w3, const float* __restrict__ b3,
    const float* __restrict__ w4, const float* __restrict__ b4,
    const float* __restrict__ w5, const float* __restrict__ b5,
    float* __restrict__ out)
{
    __shared__ float  wbuf[2 * TILE_FLOATS];   // 32 KB weight staging
    __shared__ float  xs0[1024];               // pooled -> h2 -> h4
    __shared__ float  xs1[1024];               // h1 -> h3
    __shared__ float4 red[256];                // 4 KB partials
    __shared__ float  l0[128], l1[128];

    const int tid  = threadIdx.x;
    const int b    = blockIdx.x >> 2;          // cluster id = batch
    const int rank = (int)ctarank();

    const uint32_t wbuf_u32 = smem_u32(wbuf);
    const uint32_t xs0_u32  = smem_u32(xs0);
    const uint32_t xs1_u32  = smem_u32(xs1);

    // ---- pooled mean (every CTA builds its own full copy) --------------------
    {
        int cnt = cu[b + 1] - cu[b];
        if (cnt < 1) cnt = 1;
        const float inv = 1.0f / ((float)cnt * (float)H_HEADS);
        if (tid < 128) {
            float s = 0.f;
            #pragma unroll
            for (int h = 0; h < H_HEADS; h++)
                s += __ldcg(&g_accum[b * C_COLS + h * 128 + tid]);
            xs0[tid] = s * inv;
        }
    }
    __syncthreads();
    CLUSTER_SYNC();                            // all CTAs done reading g_accum[b]

    // reset this batch's accumulator (each rank clears a quarter)
    for (int i = tid; i < 256; i += 256)
        g_accum[b * C_COLS + rank * 256 + i] = 0.f;

    // ---- L1: 128 -> 1024, silu.  SLICE=256, KTILE=16, 8 tiles ----------------
    do_layer_async< 128, 1024, 256,  16, true >(w1, b1, rank, tid, xs0,
                                                wbuf, wbuf_u32, red, xs1_u32);
    CLUSTER_SYNC();

    // ---- L2: 1024 -> 256, no act. SLICE=64, KTILE=64, 16 tiles ---------------
    do_layer_async<1024,  256,  64,  64, false>(w2, b2, rank, tid, xs1,
                                                wbuf, wbuf_u32, red, xs0_u32);
    CLUSTER_SYNC();

    // ---- L3: 256 -> 512, silu.  SLICE=128, KTILE=32, 8 tiles -----------------
    do_layer_async< 256,  512, 128,  32, true >(w3, b3, rank, tid, xs0,
                                                wbuf, wbuf_u32, red, xs1_u32);
    CLUSTER_SYNC();

    // ---- L4: 512 -> 128, silu.  SLICE=32, KTILE=128, 4 tiles -----------------
    do_layer_async< 512,  128,  32, 128, true >(w4, b4, rank, tid, xs1,
                                                wbuf, wbuf_u32, red, xs0_u32);
    CLUSTER_SYNC();

    // ---- L5: 128 -> 2, argmax, output (rank 0 only) --------------------------
    if (rank == 0) {
        if (tid < 128) {
            float v = xs0[tid];
            l0[tid] = v * w5[tid * 2 + 0];
            l1[tid] = v * w5[tid * 2 + 1];
        }
        __syncthreads();
        #pragma unroll
        for (int stride = 64; stride > 0; stride >>= 1) {
            if (tid < stride) {
                l0[tid] += l0[tid + stride];
                l1[tid] += l1[tid + stride];
            }
            __syncthreads();
        }
        if (tid == 0) {
            float lg0 = l0[0] + b5[0];
            float lg1 = l1[0] + b5[1];
            float z = (lg1 > lg0) ? 1.0f : 0.0f;   // argmax; tie -> class 0
            #pragma unroll
            for (int h = 0; h < H_HEADS; h++)
                out[b * H_HEADS + h] = z;
        }
    }
    // no CTA exits while peers may still write its smem
    CLUSTER_SYNC();
}

// ---------------- launch --------------------------------------------------------
extern "C" void kernel_launch(void* const* d_in, const int* in_sizes, int n_in,
                              void* d_out, int out_size)
{
    const float* x  = (const float*)d_in[0];
    const int*   cu = (const int*)  d_in[1];
    const float* w1 = (const float*)d_in[2];
    const float* b1 = (const float*)d_in[3];
    const float* w2 = (const float*)d_in[4];
    const float* b2 = (const float*)d_in[5];
    const float* w3 = (const float*)d_in[6];
    const float* b3 = (const float*)d_in[7];
    const float* w4 = (const float*)d_in[8];
    const float* b4 = (const float*)d_in[9];
    const float* w5 = (const float*)d_in[10];
    const float* b5 = (const float*)d_in[11];

    reduce_kernel<<<RBLK, 256>>>((const float4*)x, cu);
    mlp_kernel<<<B_SEG * CLUSTER, 256>>>(cu, w1, b1, w2, b2, w3, b3,
                                         w4, b4, w5, b5, (float*)d_out);
}